// round 11
// baseline (speedup 1.0000x reference)
#include <cuda_runtime.h>
#include <cuda_fp16.h>
#include <cstdint>
#include <cstring>

// ============================================================
// LSTM on GB300, base-target ISA (no tcgen05 available).
// R11 (= R10 resubmit after infra failure):
//  - per-pair private A rings + 2-warp named barriers replace
//    CTA-wide per-iteration syncthreads (10 -> 4 per step)
//  - tanh.approx activations (5 MUFU/elem vs 10)
//  - 512 threads/CTA, warps 4M x 2N x 2K; pair = (wm,wk), wn 0/1
//  - ONE persistent kernel, all 256 steps; W in SMEM; c in regs;
//    per-m-half grid barrier (64 CTAs each, release-atomic).
//  - P-table slice in SMEM; hoisted token load; float4 epilogue.
// ============================================================

constexpr int BATCH = 256;
constexpr int SEQ   = 256;
constexpr int HID   = 1024;
constexpr int G4    = 4096;
constexpr int NTILE = 64;
constexpr int MTILE = 128;
constexpr int KCE   = 64;             // K elems (fp16) per chunk = 128 bytes
constexpr int WPITCH = 2048;          // swizzled, no pad
constexpr int ZPITCH = 68;            // floats
constexpr int THREADS = 512;

constexpr int SM_W  = 0;
constexpr int SM_A  = NTILE * WPITCH;            // 131072
constexpr int PSTAGE = 4096;                     // 32 rows x 128B per pair-chunk
constexpr int PRING  = 3 * PSTAGE;               // 12288 per pair
constexpr int SM_P  = SM_A + 8 * PRING;          // 229376
constexpr int ZBYTES = MTILE * ZPITCH * 4;       // 34816 (z0+z1 alias A rings)
constexpr int SMEM_TOTAL = SM_P + 10 * NTILE * 4;   // 231936

// ---------------- persistent device state ----------------
__device__ __half g_Wf[(size_t)G4 * HID];        // 8 MB, permuted fp16 weights
__device__ float  g_P[(size_t)10 * G4];          // permuted xproj table
__device__ __half g_hf[2][(size_t)BATCH * HID];  // h double buffer (fp16)
__device__ int    g_x[BATCH * SEQ];              // canonical int32 tokens
__device__ unsigned g_bar2[2];                   // per-m-half barriers

// ---------------- helpers ----------------
__device__ __forceinline__ uint32_t smem_u32(const void* p) {
    uint32_t a;
    asm("{ .reg .u64 t; cvta.to.shared.u64 t, %1; cvt.u32.u64 %0, t; }" : "=r"(a) : "l"(p));
    return a;
}
__device__ __forceinline__ void cp16(uint32_t dst, const void* src) {
    asm volatile("cp.async.cg.shared.global [%0], [%1], 16;" :: "r"(dst), "l"(src));
}
__device__ __forceinline__ void ldm_x4(uint32_t* r, uint32_t addr) {
    asm volatile("ldmatrix.sync.aligned.m8n8.x4.shared.b16 {%0,%1,%2,%3}, [%4];"
        : "=r"(r[0]), "=r"(r[1]), "=r"(r[2]), "=r"(r[3]) : "r"(addr));
}
__device__ __forceinline__ void mma_f16(float* d, const uint32_t* a, const uint32_t* b) {
    asm volatile("mma.sync.aligned.m16n8k16.row.col.f32.f16.f16.f32 "
        "{%0,%1,%2,%3}, {%4,%5,%6,%7}, {%8,%9}, {%0,%1,%2,%3};"
        : "+f"(d[0]), "+f"(d[1]), "+f"(d[2]), "+f"(d[3])
        : "r"(a[0]), "r"(a[1]), "r"(a[2]), "r"(a[3]), "r"(b[0]), "r"(b[1]));
}
__device__ __forceinline__ void bar_pair(int id) {
    asm volatile("bar.sync %0, 64;" :: "r"(id) : "memory");
}
__device__ __forceinline__ float tanh_fast(float x) {
    float y; asm("tanh.approx.f32 %0, %1;" : "=f"(y) : "f"(x)); return y;
}
__device__ __forceinline__ float sig_fast(float x) {
    return fmaf(0.5f, tanh_fast(0.5f * x), 0.5f);
}

// ---------------- prep kernels ----------------
__global__ void zero_kernel() {
    int i = blockIdx.x * blockDim.x + threadIdx.x;
    if (i < BATCH * HID) g_hf[0][i] = __float2half(0.0f);
    if (i == 0) { g_bar2[0] = 0u; g_bar2[1] = 0u; }
}

// Detect whether x is int64 or int32 and canonicalize to g_x (int32).
__global__ void detect_convert_x(const void* xs) {
    __shared__ unsigned acc[256];
    const unsigned* w = (const unsigned*)xs;
    unsigned o = 0;
    for (int i = threadIdx.x; i < BATCH * SEQ / 2; i += 256) o |= w[2 * i + 1];
    acc[threadIdx.x] = o;
    __syncthreads();
    for (int s = 128; s > 0; s >>= 1) {
        if (threadIdx.x < s) acc[threadIdx.x] |= acc[threadIdx.x + s];
        __syncthreads();
    }
    if (acc[0] == 0u) {   // int64 layout
        const long long* p = (const long long*)xs;
        for (int i = threadIdx.x; i < BATCH * SEQ; i += 256) g_x[i] = (int)p[i];
    } else {              // int32 layout
        const int* p = (const int*)xs;
        for (int i = threadIdx.x; i < BATCH * SEQ; i += 256) g_x[i] = p[i];
    }
}

// column n -> (gate = (n%64)/16, j = (n/64)*16 + n%16)
__global__ void prep_kernel(const float* __restrict__ Wgx, const float* __restrict__ Wix,
                            const float* __restrict__ Wfx, const float* __restrict__ Wox,
                            const float* __restrict__ Wgh, const float* __restrict__ Wih,
                            const float* __restrict__ Wfh, const float* __restrict__ Woh,
                            const float* __restrict__ embed,
                            const float* __restrict__ bg, const float* __restrict__ bi,
                            const float* __restrict__ bf_, const float* __restrict__ bo) {
    int n = blockIdx.x;
    int within = n & 63;
    int gate = within >> 4;
    int j = ((n >> 6) << 4) + (within & 15);

    const float* Wh = gate == 0 ? Wgh : gate == 1 ? Wih : gate == 2 ? Wfh : Woh;
    const float* src = Wh + (size_t)j * HID;
    __half* d = g_Wf + (size_t)n * HID;
    for (int k = threadIdx.x; k < HID; k += blockDim.x)
        d[k] = __float2half(src[k]);

    if (threadIdx.x < 10) {
        int v = threadIdx.x;
        const float* Wx = gate == 0 ? Wgx : gate == 1 ? Wix : gate == 2 ? Wfx : Wox;
        const float* bb = gate == 0 ? bg : gate == 1 ? bi : gate == 2 ? bf_ : bo;
        float s = bb[j];
#pragma unroll
        for (int e = 0; e < 10; e++) s += Wx[j * 10 + e] * embed[v * 10 + e];
        g_P[(size_t)v * G4 + n] = s;
    }
}

// ---------------- persistent LSTM kernel ----------------
__global__ __launch_bounds__(THREADS, 1) void lstm_persist() {
    extern __shared__ char sm[];
    uint32_t sb = smem_u32(sm);
    int tid = threadIdx.x;
    int lane = tid & 31, wid = tid >> 5;
    int wm = wid & 3;                 // 4 M groups (32 rows each)
    int wn = (wid >> 2) & 1;          // 2 N groups (32 cols each)
    int wk = wid >> 3;                // 2 K groups (8 chunks each)
    int pair_id = wm * 2 + wk;        // 0..7; pair = {wn=0, wn=1}
    int bar_id = 1 + pair_id;         // named barriers 1..8
    int ntile = blockIdx.x;           // 0..63
    int my = blockIdx.y;
    int m0 = my * MTILE;              // 0 or 128
    int n0 = ntile * NTILE;

    // ---- load W (fp16, full K, swizzled) into SMEM once ----
    for (int i = tid; i < NTILE * 128; i += THREADS) {
        int r = i >> 7, s16 = i & 127;
        uint32_t slot = (uint32_t)(s16 ^ (r & 7));
        cp16(sb + SM_W + r * WPITCH + (slot << 4),
             g_Wf + (size_t)(n0 + r) * HID + s16 * 8);
    }
    asm volatile("cp.async.commit_group;" ::: "memory");
    // ---- load P slice (10 x 64 floats) into SMEM once ----
    float* sp = (float*)(sm + SM_P);
    for (int i = tid; i < 10 * NTILE; i += THREADS)
        sp[i] = g_P[(size_t)(i >> 6) * G4 + n0 + (i & 63)];
    asm volatile("cp.async.wait_group 0;" ::: "memory");
    __syncthreads();

    // epilogue ownership: thread -> (b_local = tid/4, 4 j's)
    int b_local = tid >> 2;
    int jb = (tid & 3) * 4;
    int b_g = m0 + b_local;
    float creg[4];
#pragma unroll
    for (int q = 0; q < 4; q++) creg[q] = 0.0f;

    // A ldmatrix lane mapping (local rows 0..31 within pair stage)
    int a_row_l = (lane & 7) + ((lane >> 3) & 1) * 8;
    int a_sel = lane & 7;
    int a_klane = (lane >> 4) & 1;
    // B ldmatrix.x4 lane mapping
    int bm = lane >> 3, br = lane & 7;
    int b_row = (bm >> 1) * 8 + br;
    int b_col0 = bm & 1;
    uint32_t b_base = sb + SM_W + (uint32_t)((wn * 32 + b_row) * WPITCH);

    uint32_t pair_base = sb + SM_A + (uint32_t)(pair_id * PRING);

    float* zb0 = (float*)(sm + SM_A);
    float* zb1 = (float*)(sm + SM_A + ZBYTES);
    float* zbw = wk == 0 ? zb0 : zb1;

    for (int t = 0; t < SEQ; t++) {
        const __half* hg = g_hf[t & 1] + (size_t)m0 * HID;
        int v = g_x[b_g * SEQ + t];          // hoisted: latency hidden by GEMM
        // this warp's A source rows (its own 32 M-rows)
        const __half* asrc = hg + (size_t)(wm * 32) * HID + wk * 8 * KCE;

        float acc[2][4][4];
#pragma unroll
        for (int mf = 0; mf < 2; mf++)
#pragma unroll
            for (int nf = 0; nf < 4; nf++)
#pragma unroll
                for (int e = 0; e < 4; e++) acc[mf][nf][e] = 0.0f;

        // load own pair's chunk i (4 cp16 per lane, warp covers half the 4KB)
        auto load_own = [&](int i) {
            uint32_t dst = pair_base + (uint32_t)((i % 3) * PSTAGE);
            const __half* src = asrc + i * KCE;
            int base = wn * 128 + lane * 4;
#pragma unroll
            for (int q = 0; q < 4; q++) {
                int slot = base + q;
                int r = slot >> 3, c16 = slot & 7;
                uint32_t so = (uint32_t)(r * 128 + ((c16 ^ (r & 7)) << 4));
                cp16(dst + so, src + (size_t)r * HID + c16 * 8);
            }
            asm volatile("cp.async.commit_group;" ::: "memory");
        };

        load_own(0);
        load_own(1);

        for (int i = 0; i < 8; i++) {
            if (i < 7) asm volatile("cp.async.wait_group 1;" ::: "memory");
            else       asm volatile("cp.async.wait_group 0;" ::: "memory");
            bar_pair(bar_id);             // partner's share of chunk i complete
            if (i < 6) load_own(i + 2);   // stage (i+2)%3: both warps consumed it at i-1

            int kc = wk * 8 + i;
            uint32_t As = pair_base + (uint32_t)((i % 3) * PSTAGE);
            uint32_t Arow0 = As + (uint32_t)(a_row_l * 128);
            int b_colk = kc * 8 + b_col0;
#pragma unroll
            for (int ksp = 0; ksp < 2; ksp++) {
                uint32_t Af[2][2][4];     // [kq][mf][4]
                uint32_t Bf[2][4][2];     // [kq][nf][2]
#pragma unroll
                for (int kq = 0; kq < 2; kq++) {
                    int ks = ksp * 2 + kq;
                    uint32_t a_off = (uint32_t)(((ks * 2 + a_klane) ^ a_sel) << 4);
                    ldm_x4(Af[kq][0], Arow0 + a_off);
                    ldm_x4(Af[kq][1], Arow0 + 16 * 128 + a_off);
                    uint32_t b_off = (uint32_t)(((b_colk + ks * 2) ^ br) << 4);
                    ldm_x4(&Bf[kq][0][0], b_base + b_off);                 // nf 0,1
                    ldm_x4(&Bf[kq][2][0], b_base + 16 * WPITCH + b_off);   // nf 2,3
                }
#pragma unroll
                for (int kq = 0; kq < 2; kq++)
#pragma unroll
                    for (int mf = 0; mf < 2; mf++)
#pragma unroll
                        for (int nf = 0; nf < 4; nf++)
                            mma_f16(acc[mf][nf], Af[kq][mf], Bf[kq][nf]);
            }
        }
        __syncthreads();   // all pairs done; safe to alias A rings with z

        // ---- write partial z (per K-group buffer) ----
        {
            int r0 = (lane >> 2), c0 = (lane & 3) * 2;
#pragma unroll
            for (int mf = 0; mf < 2; mf++)
#pragma unroll
                for (int nf = 0; nf < 4; nf++) {
                    int row = wm * 32 + mf * 16 + r0;
                    int col = wn * 32 + nf * 8 + c0;
                    zbw[row * ZPITCH + col]           = acc[mf][nf][0];
                    zbw[row * ZPITCH + col + 1]       = acc[mf][nf][1];
                    zbw[(row + 8) * ZPITCH + col]     = acc[mf][nf][2];
                    zbw[(row + 8) * ZPITCH + col + 1] = acc[mf][nf][3];
                }
        }
        __syncthreads();

        // ---- epilogue: z = zb0 + zb1 + P; gates; c/h update (float4 LDS) ----
        {
            const float* Pr = sp + v * NTILE;
            const float* z0 = zb0 + b_local * ZPITCH;
            const float* z1 = zb1 + b_local * ZPITCH;
            union F4 { float4 v; float f[4]; };
            F4 zg, zi, zf, zo;
            {
                float4 a, b, p;
                a = *(const float4*)(z0 + jb);      b = *(const float4*)(z1 + jb);      p = *(const float4*)(Pr + jb);
                zg.v = make_float4(a.x + b.x + p.x, a.y + b.y + p.y, a.z + b.z + p.z, a.w + b.w + p.w);
                a = *(const float4*)(z0 + 16 + jb); b = *(const float4*)(z1 + 16 + jb); p = *(const float4*)(Pr + 16 + jb);
                zi.v = make_float4(a.x + b.x + p.x, a.y + b.y + p.y, a.z + b.z + p.z, a.w + b.w + p.w);
                a = *(const float4*)(z0 + 32 + jb); b = *(const float4*)(z1 + 32 + jb); p = *(const float4*)(Pr + 32 + jb);
                zf.v = make_float4(a.x + b.x + p.x, a.y + b.y + p.y, a.z + b.z + p.z, a.w + b.w + p.w);
                a = *(const float4*)(z0 + 48 + jb); b = *(const float4*)(z1 + 48 + jb); p = *(const float4*)(Pr + 48 + jb);
                zo.v = make_float4(a.x + b.x + p.x, a.y + b.y + p.y, a.z + b.z + p.z, a.w + b.w + p.w);
            }
            __half hh[4];
#pragma unroll
            for (int jj = 0; jj < 4; jj++) {
                float g  = tanh_fast(zg.f[jj]);
                float ig = sig_fast(zi.f[jj]);
                float fg = sig_fast(zf.f[jj]);
                float og = sig_fast(zo.f[jj]);
                float cn = g * ig + creg[jj] * fg;
                creg[jj] = cn;
                hh[jj] = __float2half(tanh_fast(cn) * og);
            }
            size_t ho = (size_t)b_g * HID + ntile * 16 + jb;
            *(uint2*)(g_hf[(t + 1) & 1] + ho) = *(const uint2*)hh;
        }

        // ---- grid barrier (per m-half; release-atomic publish) ----
        __syncthreads();
        if (tid == 0) {
            unsigned dummy;
            asm volatile("atom.add.release.gpu.u32 %0, [%1], 1;"
                         : "=r"(dummy) : "l"(&g_bar2[my]) : "memory");
            unsigned tgt = 64u * (unsigned)(t + 1);
            unsigned vv;
            do {
                asm volatile("ld.acquire.gpu.u32 %0, [%1];" : "=r"(vv) : "l"(&g_bar2[my]));
            } while (vv < tgt);
        }
        __syncthreads();
    }
}

// ---------------- final projection ----------------
__global__ void final_proj_kernel(const float* __restrict__ Wp, const float* __restrict__ bp,
                                  float* __restrict__ out) {
    int b = blockIdx.x;
    int tid = threadIdx.x;   // 128
    const __half* h = g_hf[0] + (size_t)b * HID;   // after 256 steps, h in buf 0
    float acc[10];
#pragma unroll
    for (int c = 0; c < 10; c++) acc[c] = 0.0f;
    for (int k = tid; k < HID; k += 128) {
        float hv = __half2float(h[k]);
#pragma unroll
        for (int c = 0; c < 10; c++) acc[c] += hv * Wp[c * HID + k];
    }
#pragma unroll
    for (int c = 0; c < 10; c++)
#pragma unroll
        for (int off = 16; off > 0; off >>= 1)
            acc[c] += __shfl_xor_sync(0xffffffffu, acc[c], off);
    __shared__ float red[4][10];
    int wid = tid >> 5, lid = tid & 31;
    if (lid == 0) {
#pragma unroll
        for (int c = 0; c < 10; c++) red[wid][c] = acc[c];
    }
    __syncthreads();
    if (tid < 10)
        out[b * 10 + tid] = red[0][tid] + red[1][tid] + red[2][tid] + red[3][tid] + bp[tid];
}

// ---------------- launch ----------------
extern "C" void kernel_launch(void* const* d_in, const int* in_sizes, int n_in,
                              void* d_out, int out_size) {
    const void*  x   = d_in[0];
    const float* embed = (const float*)d_in[1];
    const float* Wgx = (const float*)d_in[2];
    const float* Wix = (const float*)d_in[3];
    const float* Wfx = (const float*)d_in[4];
    const float* Wox = (const float*)d_in[5];
    const float* Wgh = (const float*)d_in[6];
    const float* Wih = (const float*)d_in[7];
    const float* Wfh = (const float*)d_in[8];
    const float* Woh = (const float*)d_in[9];
    const float* Wph = (const float*)d_in[10];
    const float* bg  = (const float*)d_in[11];
    const float* bi  = (const float*)d_in[12];
    const float* bf_ = (const float*)d_in[13];
    const float* bo  = (const float*)d_in[14];
    const float* bp  = (const float*)d_in[15];

    cudaFuncSetAttribute(lstm_persist, cudaFuncAttributeMaxDynamicSharedMemorySize, SMEM_TOTAL);

    zero_kernel<<<(BATCH * HID + 255) / 256, 256>>>();
    detect_convert_x<<<1, 256>>>(x);
    prep_kernel<<<G4, 128>>>(Wgx, Wix, Wfx, Wox, Wgh, Wih, Wfh, Woh, embed, bg, bi, bf_, bo);

    dim3 grid(G4 / NTILE, BATCH / MTILE);   // (64, 2) = 128 CTAs, all resident
    lstm_persist<<<grid, THREADS, SMEM_TOTAL>>>();

    final_proj_kernel<<<BATCH, 128>>>(Wph, bp, (float*)d_out);
}

// round 12
// speedup vs baseline: 1.1826x; 1.1826x over previous
#include <cuda_runtime.h>
#include <cuda_fp16.h>
#include <cstdint>
#include <cstring>

// ============================================================
// LSTM on GB300, base-target ISA (no tcgen05 available).
// R12 = R11 with the load-coalescing fix:
//   load_own lane mapping now DENSE (slot = wn*128 + q*32 + lane)
//   -> each cp.async instruction covers 4 full 128B rows
//   (R11 had 64B-stride fragmentation: L2 5.5%->24.8%, regressed).
//  - per-pair private A rings + 2-warp named barriers
//  - tanh.approx activations
//  - 512 threads/CTA, warps 4M x 2N x 2K; pair = (wm,wk), wn 0/1
//  - ONE persistent kernel; W in SMEM; c in regs;
//    per-m-half grid barrier (64 CTAs each, release-atomic).
// ============================================================

constexpr int BATCH = 256;
constexpr int SEQ   = 256;
constexpr int HID   = 1024;
constexpr int G4    = 4096;
constexpr int NTILE = 64;
constexpr int MTILE = 128;
constexpr int KCE   = 64;             // K elems (fp16) per chunk = 128 bytes
constexpr int WPITCH = 2048;          // swizzled, no pad
constexpr int ZPITCH = 68;            // floats
constexpr int THREADS = 512;

constexpr int SM_W  = 0;
constexpr int SM_A  = NTILE * WPITCH;            // 131072
constexpr int PSTAGE = 4096;                     // 32 rows x 128B per pair-chunk
constexpr int PRING  = 3 * PSTAGE;               // 12288 per pair
constexpr int SM_P  = SM_A + 8 * PRING;          // 229376
constexpr int ZBYTES = MTILE * ZPITCH * 4;       // 34816 (z0+z1 alias A rings)
constexpr int SMEM_TOTAL = SM_P + 10 * NTILE * 4;   // 231936

// ---------------- persistent device state ----------------
__device__ __half g_Wf[(size_t)G4 * HID];        // 8 MB, permuted fp16 weights
__device__ float  g_P[(size_t)10 * G4];          // permuted xproj table
__device__ __half g_hf[2][(size_t)BATCH * HID];  // h double buffer (fp16)
__device__ int    g_x[BATCH * SEQ];              // canonical int32 tokens
__device__ unsigned g_bar2[2];                   // per-m-half barriers

// ---------------- helpers ----------------
__device__ __forceinline__ uint32_t smem_u32(const void* p) {
    uint32_t a;
    asm("{ .reg .u64 t; cvta.to.shared.u64 t, %1; cvt.u32.u64 %0, t; }" : "=r"(a) : "l"(p));
    return a;
}
__device__ __forceinline__ void cp16(uint32_t dst, const void* src) {
    asm volatile("cp.async.cg.shared.global [%0], [%1], 16;" :: "r"(dst), "l"(src));
}
__device__ __forceinline__ void ldm_x4(uint32_t* r, uint32_t addr) {
    asm volatile("ldmatrix.sync.aligned.m8n8.x4.shared.b16 {%0,%1,%2,%3}, [%4];"
        : "=r"(r[0]), "=r"(r[1]), "=r"(r[2]), "=r"(r[3]) : "r"(addr));
}
__device__ __forceinline__ void mma_f16(float* d, const uint32_t* a, const uint32_t* b) {
    asm volatile("mma.sync.aligned.m16n8k16.row.col.f32.f16.f16.f32 "
        "{%0,%1,%2,%3}, {%4,%5,%6,%7}, {%8,%9}, {%0,%1,%2,%3};"
        : "+f"(d[0]), "+f"(d[1]), "+f"(d[2]), "+f"(d[3])
        : "r"(a[0]), "r"(a[1]), "r"(a[2]), "r"(a[3]), "r"(b[0]), "r"(b[1]));
}
__device__ __forceinline__ void bar_pair(int id) {
    asm volatile("bar.sync %0, 64;" :: "r"(id) : "memory");
}
__device__ __forceinline__ float tanh_fast(float x) {
    float y; asm("tanh.approx.f32 %0, %1;" : "=f"(y) : "f"(x)); return y;
}
__device__ __forceinline__ float sig_fast(float x) {
    return fmaf(0.5f, tanh_fast(0.5f * x), 0.5f);
}

// ---------------- prep kernels ----------------
__global__ void zero_kernel() {
    int i = blockIdx.x * blockDim.x + threadIdx.x;
    if (i < BATCH * HID) g_hf[0][i] = __float2half(0.0f);
    if (i == 0) { g_bar2[0] = 0u; g_bar2[1] = 0u; }
}

// Detect whether x is int64 or int32 and canonicalize to g_x (int32).
__global__ void detect_convert_x(const void* xs) {
    __shared__ unsigned acc[256];
    const unsigned* w = (const unsigned*)xs;
    unsigned o = 0;
    for (int i = threadIdx.x; i < BATCH * SEQ / 2; i += 256) o |= w[2 * i + 1];
    acc[threadIdx.x] = o;
    __syncthreads();
    for (int s = 128; s > 0; s >>= 1) {
        if (threadIdx.x < s) acc[threadIdx.x] |= acc[threadIdx.x + s];
        __syncthreads();
    }
    if (acc[0] == 0u) {   // int64 layout
        const long long* p = (const long long*)xs;
        for (int i = threadIdx.x; i < BATCH * SEQ; i += 256) g_x[i] = (int)p[i];
    } else {              // int32 layout
        const int* p = (const int*)xs;
        for (int i = threadIdx.x; i < BATCH * SEQ; i += 256) g_x[i] = p[i];
    }
}

// column n -> (gate = (n%64)/16, j = (n/64)*16 + n%16)
__global__ void prep_kernel(const float* __restrict__ Wgx, const float* __restrict__ Wix,
                            const float* __restrict__ Wfx, const float* __restrict__ Wox,
                            const float* __restrict__ Wgh, const float* __restrict__ Wih,
                            const float* __restrict__ Wfh, const float* __restrict__ Woh,
                            const float* __restrict__ embed,
                            const float* __restrict__ bg, const float* __restrict__ bi,
                            const float* __restrict__ bf_, const float* __restrict__ bo) {
    int n = blockIdx.x;
    int within = n & 63;
    int gate = within >> 4;
    int j = ((n >> 6) << 4) + (within & 15);

    const float* Wh = gate == 0 ? Wgh : gate == 1 ? Wih : gate == 2 ? Wfh : Woh;
    const float* src = Wh + (size_t)j * HID;
    __half* d = g_Wf + (size_t)n * HID;
    for (int k = threadIdx.x; k < HID; k += blockDim.x)
        d[k] = __float2half(src[k]);

    if (threadIdx.x < 10) {
        int v = threadIdx.x;
        const float* Wx = gate == 0 ? Wgx : gate == 1 ? Wix : gate == 2 ? Wfx : Wox;
        const float* bb = gate == 0 ? bg : gate == 1 ? bi : gate == 2 ? bf_ : bo;
        float s = bb[j];
#pragma unroll
        for (int e = 0; e < 10; e++) s += Wx[j * 10 + e] * embed[v * 10 + e];
        g_P[(size_t)v * G4 + n] = s;
    }
}

// ---------------- persistent LSTM kernel ----------------
__global__ __launch_bounds__(THREADS, 1) void lstm_persist() {
    extern __shared__ char sm[];
    uint32_t sb = smem_u32(sm);
    int tid = threadIdx.x;
    int lane = tid & 31, wid = tid >> 5;
    int wm = wid & 3;                 // 4 M groups (32 rows each)
    int wn = (wid >> 2) & 1;          // 2 N groups (32 cols each)
    int wk = wid >> 3;                // 2 K groups (8 chunks each)
    int pair_id = wm * 2 + wk;        // 0..7; pair = {wn=0, wn=1}
    int bar_id = 1 + pair_id;         // named barriers 1..8
    int ntile = blockIdx.x;           // 0..63
    int my = blockIdx.y;
    int m0 = my * MTILE;              // 0 or 128
    int n0 = ntile * NTILE;

    // ---- load W (fp16, full K, swizzled) into SMEM once ----
    for (int i = tid; i < NTILE * 128; i += THREADS) {
        int r = i >> 7, s16 = i & 127;
        uint32_t slot = (uint32_t)(s16 ^ (r & 7));
        cp16(sb + SM_W + r * WPITCH + (slot << 4),
             g_Wf + (size_t)(n0 + r) * HID + s16 * 8);
    }
    asm volatile("cp.async.commit_group;" ::: "memory");
    // ---- load P slice (10 x 64 floats) into SMEM once ----
    float* sp = (float*)(sm + SM_P);
    for (int i = tid; i < 10 * NTILE; i += THREADS)
        sp[i] = g_P[(size_t)(i >> 6) * G4 + n0 + (i & 63)];
    asm volatile("cp.async.wait_group 0;" ::: "memory");
    __syncthreads();

    // epilogue ownership: thread -> (b_local = tid/4, 4 j's)
    int b_local = tid >> 2;
    int jb = (tid & 3) * 4;
    int b_g = m0 + b_local;
    float creg[4];
#pragma unroll
    for (int q = 0; q < 4; q++) creg[q] = 0.0f;

    // A ldmatrix lane mapping (local rows 0..31 within pair stage)
    int a_row_l = (lane & 7) + ((lane >> 3) & 1) * 8;
    int a_sel = lane & 7;
    int a_klane = (lane >> 4) & 1;
    // B ldmatrix.x4 lane mapping
    int bm = lane >> 3, br = lane & 7;
    int b_row = (bm >> 1) * 8 + br;
    int b_col0 = bm & 1;
    uint32_t b_base = sb + SM_W + (uint32_t)((wn * 32 + b_row) * WPITCH);

    uint32_t pair_base = sb + SM_A + (uint32_t)(pair_id * PRING);

    float* zb0 = (float*)(sm + SM_A);
    float* zb1 = (float*)(sm + SM_A + ZBYTES);
    float* zbw = wk == 0 ? zb0 : zb1;

    for (int t = 0; t < SEQ; t++) {
        const __half* hg = g_hf[t & 1] + (size_t)m0 * HID;
        int v = g_x[b_g * SEQ + t];          // hoisted: latency hidden by GEMM
        // this warp's A source rows (its own 32 M-rows)
        const __half* asrc = hg + (size_t)(wm * 32) * HID + wk * 8 * KCE;

        float acc[2][4][4];
#pragma unroll
        for (int mf = 0; mf < 2; mf++)
#pragma unroll
            for (int nf = 0; nf < 4; nf++)
#pragma unroll
                for (int e = 0; e < 4; e++) acc[mf][nf][e] = 0.0f;

        // load own pair's chunk i. DENSE lane mapping: instruction q covers
        // slots [q*32, q*32+32) = 4 complete 128B rows (4 lines, all sectors).
        auto load_own = [&](int i) {
            uint32_t dst = pair_base + (uint32_t)((i % 3) * PSTAGE);
            const __half* src = asrc + i * KCE;
#pragma unroll
            for (int q = 0; q < 4; q++) {
                int slot = wn * 128 + q * 32 + lane;
                int r = slot >> 3, c16 = slot & 7;
                uint32_t so = (uint32_t)(r * 128 + ((c16 ^ (r & 7)) << 4));
                cp16(dst + so, src + (size_t)r * HID + c16 * 8);
            }
            asm volatile("cp.async.commit_group;" ::: "memory");
        };

        load_own(0);
        load_own(1);

        for (int i = 0; i < 8; i++) {
            if (i < 7) asm volatile("cp.async.wait_group 1;" ::: "memory");
            else       asm volatile("cp.async.wait_group 0;" ::: "memory");
            bar_pair(bar_id);             // partner's share of chunk i complete
            if (i < 6) load_own(i + 2);   // stage (i+2)%3: both warps consumed it at i-1

            int kc = wk * 8 + i;
            uint32_t As = pair_base + (uint32_t)((i % 3) * PSTAGE);
            uint32_t Arow0 = As + (uint32_t)(a_row_l * 128);
            int b_colk = kc * 8 + b_col0;
#pragma unroll
            for (int ksp = 0; ksp < 2; ksp++) {
                uint32_t Af[2][2][4];     // [kq][mf][4]
                uint32_t Bf[2][4][2];     // [kq][nf][2]
#pragma unroll
                for (int kq = 0; kq < 2; kq++) {
                    int ks = ksp * 2 + kq;
                    uint32_t a_off = (uint32_t)(((ks * 2 + a_klane) ^ a_sel) << 4);
                    ldm_x4(Af[kq][0], Arow0 + a_off);
                    ldm_x4(Af[kq][1], Arow0 + 16 * 128 + a_off);
                    uint32_t b_off = (uint32_t)(((b_colk + ks * 2) ^ br) << 4);
                    ldm_x4(&Bf[kq][0][0], b_base + b_off);                 // nf 0,1
                    ldm_x4(&Bf[kq][2][0], b_base + 16 * WPITCH + b_off);   // nf 2,3
                }
#pragma unroll
                for (int kq = 0; kq < 2; kq++)
#pragma unroll
                    for (int mf = 0; mf < 2; mf++)
#pragma unroll
                        for (int nf = 0; nf < 4; nf++)
                            mma_f16(acc[mf][nf], Af[kq][mf], Bf[kq][nf]);
            }
        }
        __syncthreads();   // all pairs done; safe to alias A rings with z

        // ---- write partial z (per K-group buffer) ----
        {
            int r0 = (lane >> 2), c0 = (lane & 3) * 2;
#pragma unroll
            for (int mf = 0; mf < 2; mf++)
#pragma unroll
                for (int nf = 0; nf < 4; nf++) {
                    int row = wm * 32 + mf * 16 + r0;
                    int col = wn * 32 + nf * 8 + c0;
                    zbw[row * ZPITCH + col]           = acc[mf][nf][0];
                    zbw[row * ZPITCH + col + 1]       = acc[mf][nf][1];
                    zbw[(row + 8) * ZPITCH + col]     = acc[mf][nf][2];
                    zbw[(row + 8) * ZPITCH + col + 1] = acc[mf][nf][3];
                }
        }
        __syncthreads();

        // ---- epilogue: z = zb0 + zb1 + P; gates; c/h update (float4 LDS) ----
        {
            const float* Pr = sp + v * NTILE;
            const float* z0 = zb0 + b_local * ZPITCH;
            const float* z1 = zb1 + b_local * ZPITCH;
            union F4 { float4 v; float f[4]; };
            F4 zg, zi, zf, zo;
            {
                float4 a, b, p;
                a = *(const float4*)(z0 + jb);      b = *(const float4*)(z1 + jb);      p = *(const float4*)(Pr + jb);
                zg.v = make_float4(a.x + b.x + p.x, a.y + b.y + p.y, a.z + b.z + p.z, a.w + b.w + p.w);
                a = *(const float4*)(z0 + 16 + jb); b = *(const float4*)(z1 + 16 + jb); p = *(const float4*)(Pr + 16 + jb);
                zi.v = make_float4(a.x + b.x + p.x, a.y + b.y + p.y, a.z + b.z + p.z, a.w + b.w + p.w);
                a = *(const float4*)(z0 + 32 + jb); b = *(const float4*)(z1 + 32 + jb); p = *(const float4*)(Pr + 32 + jb);
                zf.v = make_float4(a.x + b.x + p.x, a.y + b.y + p.y, a.z + b.z + p.z, a.w + b.w + p.w);
                a = *(const float4*)(z0 + 48 + jb); b = *(const float4*)(z1 + 48 + jb); p = *(const float4*)(Pr + 48 + jb);
                zo.v = make_float4(a.x + b.x + p.x, a.y + b.y + p.y, a.z + b.z + p.z, a.w + b.w + p.w);
            }
            __half hh[4];
#pragma unroll
            for (int jj = 0; jj < 4; jj++) {
                float g  = tanh_fast(zg.f[jj]);
                float ig = sig_fast(zi.f[jj]);
                float fg = sig_fast(zf.f[jj]);
                float og = sig_fast(zo.f[jj]);
                float cn = g * ig + creg[jj] * fg;
                creg[jj] = cn;
                hh[jj] = __float2half(tanh_fast(cn) * og);
            }
            size_t ho = (size_t)b_g * HID + ntile * 16 + jb;
            *(uint2*)(g_hf[(t + 1) & 1] + ho) = *(const uint2*)hh;
        }

        // ---- grid barrier (per m-half; release-atomic publish) ----
        __syncthreads();
        if (tid == 0) {
            unsigned dummy;
            asm volatile("atom.add.release.gpu.u32 %0, [%1], 1;"
                         : "=r"(dummy) : "l"(&g_bar2[my]) : "memory");
            unsigned tgt = 64u * (unsigned)(t + 1);
            unsigned vv;
            do {
                asm volatile("ld.acquire.gpu.u32 %0, [%1];" : "=r"(vv) : "l"(&g_bar2[my]));
            } while (vv < tgt);
        }
        __syncthreads();
    }
}

// ---------------- final projection ----------------
__global__ void final_proj_kernel(const float* __restrict__ Wp, const float* __restrict__ bp,
                                  float* __restrict__ out) {
    int b = blockIdx.x;
    int tid = threadIdx.x;   // 128
    const __half* h = g_hf[0] + (size_t)b * HID;   // after 256 steps, h in buf 0
    float acc[10];
#pragma unroll
    for (int c = 0; c < 10; c++) acc[c] = 0.0f;
    for (int k = tid; k < HID; k += 128) {
        float hv = __half2float(h[k]);
#pragma unroll
        for (int c = 0; c < 10; c++) acc[c] += hv * Wp[c * HID + k];
    }
#pragma unroll
    for (int c = 0; c < 10; c++)
#pragma unroll
        for (int off = 16; off > 0; off >>= 1)
            acc[c] += __shfl_xor_sync(0xffffffffu, acc[c], off);
    __shared__ float red[4][10];
    int wid = tid >> 5, lid = tid & 31;
    if (lid == 0) {
#pragma unroll
        for (int c = 0; c < 10; c++) red[wid][c] = acc[c];
    }
    __syncthreads();
    if (tid < 10)
        out[b * 10 + tid] = red[0][tid] + red[1][tid] + red[2][tid] + red[3][tid] + bp[tid];
}

// ---------------- launch ----------------
extern "C" void kernel_launch(void* const* d_in, const int* in_sizes, int n_in,
                              void* d_out, int out_size) {
    const void*  x   = d_in[0];
    const float* embed = (const float*)d_in[1];
    const float* Wgx = (const float*)d_in[2];
    const float* Wix = (const float*)d_in[3];
    const float* Wfx = (const float*)d_in[4];
    const float* Wox = (const float*)d_in[5];
    const float* Wgh = (const float*)d_in[6];
    const float* Wih = (const float*)d_in[7];
    const float* Wfh = (const float*)d_in[8];
    const float* Woh = (const float*)d_in[9];
    const float* Wph = (const float*)d_in[10];
    const float* bg  = (const float*)d_in[11];
    const float* bi  = (const float*)d_in[12];
    const float* bf_ = (const float*)d_in[13];
    const float* bo  = (const float*)d_in[14];
    const float* bp  = (const float*)d_in[15];

    cudaFuncSetAttribute(lstm_persist, cudaFuncAttributeMaxDynamicSharedMemorySize, SMEM_TOTAL);

    zero_kernel<<<(BATCH * HID + 255) / 256, 256>>>();
    detect_convert_x<<<1, 256>>>(x);
    prep_kernel<<<G4, 128>>>(Wgx, Wix, Wfx, Wox, Wgh, Wih, Wfh, Woh, embed, bg, bi, bf_, bo);

    dim3 grid(G4 / NTILE, BATCH / MTILE);   // (64, 2) = 128 CTAs, all resident
    lstm_persist<<<grid, THREADS, SMEM_TOTAL>>>();

    final_proj_kernel<<<BATCH, 128>>>(Wph, bp, (float*)d_out);
}